// round 14
// baseline (speedup 1.0000x reference)
#include <cuda_runtime.h>
#include <cuda_bf16.h>
#include <mma.h>
#include <cstdint>

using namespace nvcuda;

#define NNODES 100000
#define NEDGES 1600000
#define HID 128
#define NGRAPH 64
#define SCAN_BLK 1024

#define LDA 36           // padded A tile stride (floats)
#define LDW 132          // padded W / C tile stride (floats)

// ---------------- scratch (device globals) -----------------------------------
__device__ uint2  g_ybf[NNODES * 32];          // y in bf16: 128 bf16/row = 32 uint2
__device__ float4 g_bufB4[NNODES * HID / 4];   // agg layer 1
__device__ float4 g_bufC4[NNODES * HID / 4];   // agg layer 2
__device__ int    g_indeg[NNODES];
__device__ int    g_btot[128];
__device__ int    g_offs[NNODES + 1];          // CSR offsets (immutable)
__device__ int    g_cursor[NNODES];            // mutable fill cursors
__device__ int    g_srcs[NEDGES];              // src ids grouped by dst
__device__ float  g_stats[4 * HID];            // layer1: [0,256), layer2: [256,512)
__device__ float  g_scsh[2 * HID];
__device__ float  g_pooled[NGRAPH * HID];
__device__ float  g_counts[NGRAPH];

// ---------------- fused zero init ---------------------------------------------
__global__ void zero_all(int* indeg, float* stats, float* pooled, float* counts, int n) {
    int i = blockIdx.x * blockDim.x + threadIdx.x;
    if (i < n) indeg[i] = 0;
    if (i < 4 * HID) stats[i] = 0.f;
    if (i < NGRAPH * HID) pooled[i] = 0.f;
    if (i < NGRAPH) counts[i] = 0.f;
}

__global__ void indeg_count(const int* __restrict__ dst, int* indeg, int E) {
    int e = blockIdx.x * blockDim.x + threadIdx.x;
    if (e < E) atomicAdd(&indeg[dst[e]], 1);
}

__global__ void block_totals(const int* __restrict__ indeg, int* btot, int n) {
    __shared__ int sh[SCAN_BLK];
    int i = blockIdx.x * SCAN_BLK + threadIdx.x;
    sh[threadIdx.x] = (i < n) ? indeg[i] : 0;
    __syncthreads();
    for (int s = SCAN_BLK / 2; s > 0; s >>= 1) {
        if (threadIdx.x < s) sh[threadIdx.x] += sh[threadIdx.x + s];
        __syncthreads();
    }
    if (threadIdx.x == 0) btot[blockIdx.x] = sh[0];
}

// scan within block + per-block offset reduced from btot; writes offs + cursor
__global__ void scan_blocks(const int* __restrict__ indeg, const int* __restrict__ btot,
                            int* offs, int* cursor, int n, int nb, int E) {
    __shared__ int sh[SCAN_BLK];
    __shared__ int off_sh[128];
    int tid = threadIdx.x;
    int i = blockIdx.x * SCAN_BLK + tid;
    int v = (i < n) ? indeg[i] : 0;
    sh[tid] = v;
    if (tid < 128) off_sh[tid] = (tid < blockIdx.x && tid < nb) ? btot[tid] : 0;
    __syncthreads();
    for (int off = 1; off < SCAN_BLK; off <<= 1) {
        int t = (tid >= off) ? sh[tid - off] : 0;
        __syncthreads();
        sh[tid] += t;
        __syncthreads();
    }
    for (int s = 64; s > 0; s >>= 1) {
        if (tid < s) off_sh[tid] += off_sh[tid + s];
        __syncthreads();
    }
    if (i < n) {
        int ex = off_sh[0] + sh[tid] - v;   // exclusive prefix
        offs[i] = ex;
        cursor[i] = ex;
    }
    if (i == n - 1) offs[n] = E;
}

__global__ void sort_fill(const int* __restrict__ src, const int* __restrict__ dst,
                          int* cursor, int* srcs, int E) {
    int e = blockIdx.x * blockDim.x + threadIdx.x;
    if (e < E) {
        int pos = atomicAdd(&cursor[dst[e]], 1);
        srcs[pos] = src[e];
    }
}

// ---------------- fused GEMM (tf32 tensor cores, padded smem) -------------------
// ybf[row] = bf16((f(A)[row] @ W) * dinv)  — only output (gather adds self term)
__global__ __launch_bounds__(256) void gemm128(
    const float* __restrict__ A, const float* __restrict__ W,
    const float* __restrict__ scsh, const int* __restrict__ indeg,
    uint2* __restrict__ ybf, int n, int mode)
{
    __shared__ __align__(16) float smem[64 * LDW];
    float* As = smem;              // 64 x LDA
    float* Ws = smem + 64 * LDA;   // 32 x LDW

    int r0 = blockIdx.x * 64;
    int tid = threadIdx.x;
    int warp = tid >> 5;
    int row_blk = warp & 3;
    int col_blk = warp >> 2;

    wmma::fragment<wmma::accumulator, 16, 16, 8, float> acc[4];
    #pragma unroll
    for (int c = 0; c < 4; c++) wmma::fill_fragment(acc[c], 0.f);

    for (int kc = 0; kc < 4; kc++) {
        #pragma unroll
        for (int t = 0; t < 2; t++) {
            int i = tid + t * 256;
            int r = i >> 3;
            int k4 = (i & 7) * 4;
            float4 v = make_float4(0.f, 0.f, 0.f, 0.f);
            if (r0 + r < n)
                v = *(const float4*)(A + (size_t)(r0 + r) * 128 + kc * 32 + k4);
            if (mode == 1) {
                v.x = (v.x == v.x) ? v.x : 0.f;
                v.y = (v.y == v.y) ? v.y : 0.f;
                v.z = (v.z == v.z) ? v.z : 0.f;
                v.w = (v.w == v.w) ? v.w : 0.f;
            } else if (mode == 2) {
                int c = kc * 32 + k4;
                v.x = fmaxf(v.x * scsh[c + 0] + scsh[128 + c + 0], 0.f);
                v.y = fmaxf(v.y * scsh[c + 1] + scsh[128 + c + 1], 0.f);
                v.z = fmaxf(v.z * scsh[c + 2] + scsh[128 + c + 2], 0.f);
                v.w = fmaxf(v.w * scsh[c + 3] + scsh[128 + c + 3], 0.f);
            }
            v.x = wmma::__float_to_tf32(v.x);
            v.y = wmma::__float_to_tf32(v.y);
            v.z = wmma::__float_to_tf32(v.z);
            v.w = wmma::__float_to_tf32(v.w);
            *(float4*)(As + r * LDA + k4) = v;
        }
        #pragma unroll
        for (int t = 0; t < 4; t++) {
            int i = tid + t * 256;
            int k = i >> 5, c4 = (i & 31) * 4;
            float4 w = *(const float4*)(W + (size_t)(kc * 32 + k) * 128 + c4);
            w.x = wmma::__float_to_tf32(w.x);
            w.y = wmma::__float_to_tf32(w.y);
            w.z = wmma::__float_to_tf32(w.z);
            w.w = wmma::__float_to_tf32(w.w);
            *(float4*)(Ws + k * LDW + c4) = w;
        }
        __syncthreads();

        #pragma unroll
        for (int kk = 0; kk < 4; kk++) {
            wmma::fragment<wmma::matrix_a, 16, 16, 8, wmma::precision::tf32, wmma::row_major> af;
            wmma::load_matrix_sync(af, As + (row_blk * 16) * LDA + kk * 8, LDA);
            #pragma unroll
            for (int c = 0; c < 4; c++) {
                wmma::fragment<wmma::matrix_b, 16, 16, 8, wmma::precision::tf32, wmma::row_major> bf;
                wmma::load_matrix_sync(bf, Ws + (kk * 8) * LDW + col_blk * 64 + c * 16, LDW);
                wmma::mma_sync(acc[c], af, bf, acc[c]);
            }
        }
        __syncthreads();
    }

    #pragma unroll
    for (int c = 0; c < 4; c++)
        wmma::store_matrix_sync(smem + (row_blk * 16) * LDW + col_blk * 64 + c * 16,
                                acc[c], LDW, wmma::mem_row_major);
    __syncthreads();

    int cg = tid & 31;
    int rg = tid >> 5;
    #pragma unroll
    for (int r = 0; r < 8; r++) {
        int row = r0 + rg * 8 + r;
        if (row < n) {
            float di = rsqrtf((float)indeg[row] + 1.0f);
            float4 v = *(float4*)(smem + (rg * 8 + r) * LDW + cg * 4);
            __nv_bfloat162 h0 = __floats2bfloat162_rn(v.x * di, v.y * di);
            __nv_bfloat162 h1 = __floats2bfloat162_rn(v.z * di, v.w * di);
            uint2 u;
            u.x = *(unsigned int*)&h0;
            u.y = *(unsigned int*)&h1;
            ybf[(size_t)row * 32 + cg] = u;
        }
    }
}

// ---------------- CSR gather + fused BN stats -----------------------------------
// agg[d] = (sum_{s in N(d)} ybf[s] + ybf[d]) * dinv[d];  one plain store per row.
// Neighbor rows read in masked batches of 8 independent loads (MLP=8).
__device__ __forceinline__ float4 unpack_bf16x4(uint2 u) {
    __nv_bfloat162 h0 = *(__nv_bfloat162*)&u.x;
    __nv_bfloat162 h1 = *(__nv_bfloat162*)&u.y;
    float2 a = __bfloat1622float2(h0);
    float2 b = __bfloat1622float2(h1);
    return make_float4(a.x, a.y, b.x, b.y);
}

__global__ __launch_bounds__(256) void gather_bn(
    const uint2* __restrict__ ybf, const int* __restrict__ srcs,
    const int* __restrict__ offs, float4* __restrict__ agg,
    float* __restrict__ stats, int n)
{
    int lane = threadIdx.x & 31;
    int warp = blockIdx.x * 8 + (threadIdx.x >> 5);
    int nwarps = gridDim.x * 8;

    float s0 = 0.f, s1 = 0.f, s2 = 0.f, s3 = 0.f;
    float q0 = 0.f, q1 = 0.f, q2 = 0.f, q3 = 0.f;

    for (int node = warp; node < n; node += nwarps) {
        int beg = offs[node], end = offs[node + 1];
        float4 acc = unpack_bf16x4(__ldg(ybf + (size_t)node * 32 + lane));  // self

        for (int i = beg; i < end; i += 8) {
            int   idx[8];
            float m[8];
            #pragma unroll
            for (int j = 0; j < 8; j++) {
                int e = i + j;
                bool ok = e < end;
                m[j]   = ok ? 1.f : 0.f;
                idx[j] = ok ? __ldg(srcs + e) : node;
            }
            uint2 raw[8];
            #pragma unroll
            for (int j = 0; j < 8; j++)
                raw[j] = __ldg(ybf + (size_t)idx[j] * 32 + lane);
            #pragma unroll
            for (int j = 0; j < 8; j++) {
                float4 v = unpack_bf16x4(raw[j]);
                acc.x += v.x * m[j];
                acc.y += v.y * m[j];
                acc.z += v.z * m[j];
                acc.w += v.w * m[j];
            }
        }

        float di = rsqrtf((float)(end - beg) + 1.0f);
        acc.x *= di; acc.y *= di; acc.z *= di; acc.w *= di;
        agg[(size_t)node * 32 + lane] = acc;

        s0 += acc.x; q0 += acc.x * acc.x;
        s1 += acc.y; q1 += acc.y * acc.y;
        s2 += acc.z; q2 += acc.z * acc.z;
        s3 += acc.w; q3 += acc.w * acc.w;
    }

    int c = lane * 4;
    atomicAdd(&stats[c + 0], s0);
    atomicAdd(&stats[c + 1], s1);
    atomicAdd(&stats[c + 2], s2);
    atomicAdd(&stats[c + 3], s3);
    atomicAdd(&stats[128 + c + 0], q0);
    atomicAdd(&stats[128 + c + 1], q1);
    atomicAdd(&stats[128 + c + 2], q2);
    atomicAdd(&stats[128 + c + 3], q3);
}

// ---------------- BN finalize -----------------------------------------------------
__global__ void bn_finalize(
    const float* __restrict__ stats, const float* __restrict__ gamma,
    const float* __restrict__ beta, float* __restrict__ scsh, int n)
{
    int c = threadIdx.x;  // 128 threads
    float invn = 1.0f / (float)n;
    float mean = stats[c] * invn;
    float var  = stats[128 + c] * invn - mean * mean;
    float sc = rsqrtf(var + 1e-5f) * gamma[c];
    scsh[c] = sc;
    scsh[128 + c] = beta[c] - mean * sc;
}

// ---------------- pooling (BN+ReLU fused; batch sorted) ----------------------------
__global__ __launch_bounds__(256) void counts_kernel(
    const int* __restrict__ batch, float* __restrict__ counts, int n)
{
    __shared__ float sc[NGRAPH];
    if (threadIdx.x < NGRAPH) sc[threadIdx.x] = 0.f;
    __syncthreads();
    for (int i = blockIdx.x * blockDim.x + threadIdx.x; i < n; i += gridDim.x * blockDim.x)
        atomicAdd(&sc[batch[i]], 1.0f);
    __syncthreads();
    if (threadIdx.x < NGRAPH) atomicAdd(&counts[threadIdx.x], sc[threadIdx.x]);
}

__global__ __launch_bounds__(128) void pool_kernel(
    const float* __restrict__ agg, const float* __restrict__ scsh,
    const int* __restrict__ batch, float* __restrict__ pooled, int n)
{
    int col = threadIdx.x;
    float sc = scsh[col], sh = scsh[128 + col];
    int r0 = blockIdx.x * 128;
    if (r0 >= n) return;
    int r1 = min(r0 + 128, n);
    int cg = batch[r0];
    float acc = 0.f;
    for (int r = r0; r < r1; r++) {
        int g = batch[r];
        if (g != cg) {
            atomicAdd(&pooled[cg * 128 + col], acc);
            acc = 0.f;
            cg = g;
        }
        acc += fmaxf(agg[(size_t)r * 128 + col] * sc + sh, 0.f);
    }
    atomicAdd(&pooled[cg * 128 + col], acc);
}

// ---------------- classifier (single block) ----------------------------------------
__global__ __launch_bounds__(256) void classifier_kernel(
    const float* __restrict__ pooled, const float* __restrict__ counts,
    const float* __restrict__ Wc1, const float* __restrict__ bc1,
    const float* __restrict__ Wc2, const float* __restrict__ bc2,
    float* __restrict__ out)
{
    __shared__ float Z[64 * 64];
    __shared__ float inv[NGRAPH];
    int tid = threadIdx.x;
    if (tid < NGRAPH) inv[tid] = 1.0f / fmaxf(counts[tid], 1.0f);
    __syncthreads();

    for (int idx = tid; idx < 64 * 64; idx += 256) {
        int r = idx >> 6, c = idx & 63;
        float dot = 0.f;
        #pragma unroll 8
        for (int k = 0; k < 128; k++)
            dot += pooled[r * 128 + k] * Wc1[k * 64 + c];
        Z[idx] = fmaxf(dot * inv[r] + bc1[c], 0.f);
    }
    __syncthreads();

    for (int idx = tid; idx < 128; idx += 256) {
        int r = idx >> 1, c = idx & 1;
        float dot = bc2[c];
        #pragma unroll
        for (int k = 0; k < 64; k++)
            dot += Z[r * 64 + k] * Wc2[k * 2 + c];
        out[idx] = (dot == dot) ? dot : 0.f;  // nan_to_num
    }
}

// ---------------- launch -------------------------------------------------------------
extern "C" void kernel_launch(void* const* d_in, const int* in_sizes, int n_in,
                              void* d_out, int out_size)
{
    const float* x     = (const float*)d_in[0];
    const int*   ei    = (const int*)d_in[1];
    const int*   batch = (const int*)d_in[2];
    const float* W1  = (const float*)d_in[3];
    // b1 = d_in[4] — exactly cancelled by BatchNorm
    const float* g1  = (const float*)d_in[5];
    const float* be1 = (const float*)d_in[6];
    const float* W2  = (const float*)d_in[7];
    // b2 = d_in[8] — same
    const float* g2  = (const float*)d_in[9];
    const float* be2 = (const float*)d_in[10];
    const float* Wc1 = (const float*)d_in[11];
    const float* bc1 = (const float*)d_in[12];
    const float* Wc2 = (const float*)d_in[13];
    const float* bc2 = (const float*)d_in[14];
    float* out = (float*)d_out;

    int n = in_sizes[0] / HID;
    int E = in_sizes[1] / 2;
    const int* srcp = ei;
    const int* dstp = ei + E;

    float *bufB, *bufC, *stats, *scsh, *pooled, *counts;
    int *indeg, *btot, *offs, *cursor, *srcs;
    uint2 *ybf;
    cudaGetSymbolAddress((void**)&ybf,    g_ybf);
    cudaGetSymbolAddress((void**)&bufB,   g_bufB4);
    cudaGetSymbolAddress((void**)&bufC,   g_bufC4);
    cudaGetSymbolAddress((void**)&indeg,  g_indeg);
    cudaGetSymbolAddress((void**)&btot,   g_btot);
    cudaGetSymbolAddress((void**)&offs,   g_offs);
    cudaGetSymbolAddress((void**)&cursor, g_cursor);
    cudaGetSymbolAddress((void**)&srcs,   g_srcs);
    cudaGetSymbolAddress((void**)&stats,  g_stats);
    cudaGetSymbolAddress((void**)&scsh,   g_scsh);
    cudaGetSymbolAddress((void**)&pooled, g_pooled);
    cudaGetSymbolAddress((void**)&counts, g_counts);

    int nb256 = (n + 255) / 256;
    int eb256 = (E + 255) / 256;
    int gemm_blocks = (n + 63) / 64;
    int scan_nb = (n + SCAN_BLK - 1) / SCAN_BLK;
    int gather_blocks = 2048;

    // side stream + events (created once; host-side objects only)
    static cudaStream_t s2 = nullptr;
    static cudaEvent_t ev_fork = nullptr, ev_join = nullptr;
    if (!s2) {
        cudaStreamCreateWithFlags(&s2, cudaStreamNonBlocking);
        cudaEventCreateWithFlags(&ev_fork, cudaEventDisableTiming);
        cudaEventCreateWithFlags(&ev_join, cudaEventDisableTiming);
    }
    cudaStream_t s0 = 0;

    // main stream: init + degree count (gemm1 needs indeg)
    zero_all<<<nb256, 256, 0, s0>>>(indeg, stats, pooled, counts, n);
    indeg_count<<<eb256, 256, 0, s0>>>(dstp, indeg, E);

    // fork: side stream builds CSR + counts, overlapping gemm1
    cudaEventRecord(ev_fork, s0);
    cudaStreamWaitEvent(s2, ev_fork, 0);
    block_totals<<<scan_nb, SCAN_BLK, 0, s2>>>(indeg, btot, n);
    scan_blocks<<<scan_nb, SCAN_BLK, 0, s2>>>(indeg, btot, offs, cursor, n, scan_nb, E);
    sort_fill<<<eb256, 256, 0, s2>>>(srcp, dstp, cursor, srcs, E);
    counts_kernel<<<64, 256, 0, s2>>>(batch, counts, n);
    cudaEventRecord(ev_join, s2);

    // main stream: layer-1 GEMM concurrent with build
    gemm128<<<gemm_blocks, 256, 0, s0>>>(x, W1, scsh, indeg, ybf, n, 1);

    // join: gather needs CSR + ybf
    cudaStreamWaitEvent(s0, ev_join, 0);

    // ---- layer 1 aggregation (BN stats fused) ----
    gather_bn<<<gather_blocks, 256, 0, s0>>>(ybf, srcs, offs, (float4*)bufB, stats, n);
    bn_finalize<<<1, 128, 0, s0>>>(stats, g1, be1, scsh, n);

    // ---- layer 2 ----
    gemm128<<<gemm_blocks, 256, 0, s0>>>(bufB, W2, scsh, indeg, ybf, n, 2);
    gather_bn<<<gather_blocks, 256, 0, s0>>>(ybf, srcs, offs, (float4*)bufC, stats + 256, n);
    bn_finalize<<<1, 128, 0, s0>>>(stats + 256, g2, be2, scsh, n);

    // ---- pool (BN+ReLU fused) + classifier ----
    pool_kernel<<<(n + 127) / 128, 128, 0, s0>>>(bufC, scsh, batch, pooled, n);
    classifier_kernel<<<1, 256, 0, s0>>>(pooled, counts, Wc1, bc1, Wc2, bc2, out);
}

// round 15
// speedup vs baseline: 2.8355x; 2.8355x over previous
#include <cuda_runtime.h>
#include <cuda_bf16.h>
#include <mma.h>
#include <cstdint>

using namespace nvcuda;

#define NNODES 100000
#define NEDGES 1600000
#define HID 128
#define NGRAPH 64
#define SCAN_BLK 1024
#define EPW 16           // edges per warp (two batches of 8)

#define LDA 36           // padded A tile stride (floats)
#define LDW 132          // padded W / C tile stride (floats)
#define A_ELEMS (64 * LDA)
#define W_ELEMS (32 * LDW)
#define GEMM_SMEM_FLOATS (2 * A_ELEMS + 2 * W_ELEMS + 256)
#define GEMM_SMEM_BYTES (GEMM_SMEM_FLOATS * 4)

// ---------------- scratch (device globals) -----------------------------------
__device__ uint2  g_ybf[NNODES * 32];          // y in bf16: 128 bf16/row = 32 uint2
__device__ float4 g_bufB4[NNODES * HID / 4];   // agg layer 1
__device__ float4 g_bufC4[NNODES * HID / 4];   // agg layer 2
__device__ int    g_indeg[NNODES];
__device__ int    g_btot[128];
__device__ int    g_cursor[NNODES];
__device__ int2   g_edges[NEDGES];             // (src,dst) sorted by dst
__device__ float  g_stats[4 * HID];            // layer1: [0,256), layer2: [256,512)
__device__ float  g_pooled[NGRAPH * HID];
__device__ float  g_counts[NGRAPH];

// ---------------- fused zero init ---------------------------------------------
__global__ void zero_all(int* indeg, float* stats, float* pooled, float* counts, int n) {
    int i = blockIdx.x * blockDim.x + threadIdx.x;
    if (i < n) indeg[i] = 0;
    if (i < 4 * HID) stats[i] = 0.f;
    if (i < NGRAPH * HID) pooled[i] = 0.f;
    if (i < NGRAPH) counts[i] = 0.f;
}

__global__ void indeg_count(const int* __restrict__ dst, int* indeg, int E) {
    int e = blockIdx.x * blockDim.x + threadIdx.x;
    if (e < E) atomicAdd(&indeg[dst[e]], 1);
}

__global__ void block_totals(const int* __restrict__ indeg, int* btot, int n) {
    __shared__ int sh[SCAN_BLK];
    int i = blockIdx.x * SCAN_BLK + threadIdx.x;
    sh[threadIdx.x] = (i < n) ? indeg[i] : 0;
    __syncthreads();
    for (int s = SCAN_BLK / 2; s > 0; s >>= 1) {
        if (threadIdx.x < s) sh[threadIdx.x] += sh[threadIdx.x + s];
        __syncthreads();
    }
    if (threadIdx.x == 0) btot[blockIdx.x] = sh[0];
}

__global__ void scan_blocks(const int* __restrict__ indeg, const int* __restrict__ btot,
                            int* cursor, int n, int nb) {
    __shared__ int sh[SCAN_BLK];
    __shared__ int off_sh[128];
    int tid = threadIdx.x;
    int i = blockIdx.x * SCAN_BLK + tid;
    int v = (i < n) ? indeg[i] : 0;
    sh[tid] = v;
    if (tid < 128) off_sh[tid] = (tid < blockIdx.x && tid < nb) ? btot[tid] : 0;
    __syncthreads();
    for (int off = 1; off < SCAN_BLK; off <<= 1) {
        int t = (tid >= off) ? sh[tid - off] : 0;
        __syncthreads();
        sh[tid] += t;
        __syncthreads();
    }
    for (int s = 64; s > 0; s >>= 1) {
        if (tid < s) off_sh[tid] += off_sh[tid + s];
        __syncthreads();
    }
    if (i < n) cursor[i] = off_sh[0] + sh[tid] - v;  // exclusive prefix
}

__global__ void sort_fill(const int* __restrict__ src, const int* __restrict__ dst,
                          int* cursor, int2* edges, int E) {
    int e = blockIdx.x * blockDim.x + threadIdx.x;
    if (e < E) {
        int d = dst[e];
        int pos = atomicAdd(&cursor[d], 1);
        edges[pos] = make_int2(src[e], d);
    }
}

// ---------------- cp.async helpers ----------------------------------------------
__device__ __forceinline__ void cpa16(float* dst_smem, const float* src, bool pred) {
    uint32_t d = (uint32_t)__cvta_generic_to_shared(dst_smem);
    int sz = pred ? 16 : 0;
    asm volatile("cp.async.cg.shared.global [%0], [%1], 16, %2;"
                 :: "r"(d), "l"(src), "r"(sz));
}
__device__ __forceinline__ void cpa_commit() {
    asm volatile("cp.async.commit_group;");
}
template <int N>
__device__ __forceinline__ void cpa_wait() {
    asm volatile("cp.async.wait_group %0;" :: "n"(N));
}

// ---------------- fused GEMM (tf32, cp.async double-buffered) -------------------
// ybf[row] = bf16((f(A)[row] @ W) * dinv);  agg[row] = same * dinv  (fp32)
// f = nan_to_num (mode 1) / BN+ReLU computed in-kernel from stats (mode 2)
__global__ __launch_bounds__(256) void gemm128(
    const float* __restrict__ A, const float* __restrict__ W,
    const float* __restrict__ gamma, const float* __restrict__ beta,
    const float* __restrict__ stats, const int* __restrict__ indeg,
    uint2* __restrict__ ybf, float* __restrict__ agg, int n, int mode)
{
    extern __shared__ __align__(16) float smem[];
    float* Ab0 = smem;
    float* Ab1 = smem + A_ELEMS;
    float* Wb0 = smem + 2 * A_ELEMS;
    float* Wb1 = smem + 2 * A_ELEMS + W_ELEMS;
    float* scsh = smem + 2 * A_ELEMS + 2 * W_ELEMS;   // 256 floats
    float* Cst = smem;                                 // epilogue alias (64 x LDW)

    int r0 = blockIdx.x * 64;
    int tid = threadIdx.x;
    int warp = tid >> 5;
    int row_blk = warp & 3;
    int col_blk = warp >> 2;

    // mode 2: compute BN scale/shift table once per block
    if (mode == 2 && tid < 128) {
        float invn = 1.0f / (float)n;
        float mean = stats[tid] * invn;
        float var  = stats[128 + tid] * invn - mean * mean;
        float sc = rsqrtf(var + 1e-5f) * gamma[tid];
        scsh[tid] = sc;
        scsh[128 + tid] = beta[tid] - mean * sc;
    }

    // issue tile kc into buffer b
    auto issue_tile = [&](int kc, float* Ab, float* Wb) {
        #pragma unroll
        for (int t = 0; t < 2; t++) {
            int i = tid + t * 256;
            int r = i >> 3;
            int k4 = (i & 7) * 4;
            bool ok = (r0 + r) < n;
            const float* src = A + (ok ? ((size_t)(r0 + r) * 128 + kc * 32 + k4) : 0);
            cpa16(Ab + r * LDA + k4, src, ok);
        }
        #pragma unroll
        for (int t = 0; t < 4; t++) {
            int i = tid + t * 256;
            int k = i >> 5, c4 = (i & 31) * 4;
            cpa16(Wb + k * LDW + c4, W + (size_t)(kc * 32 + k) * 128 + c4, true);
        }
        cpa_commit();
    };

    wmma::fragment<wmma::accumulator, 16, 16, 8, float> acc[4];
    #pragma unroll
    for (int c = 0; c < 4; c++) wmma::fill_fragment(acc[c], 0.f);

    issue_tile(0, Ab0, Wb0);

    #pragma unroll
    for (int kc = 0; kc < 4; kc++) {
        float* Ab = (kc & 1) ? Ab1 : Ab0;
        float* Wb = (kc & 1) ? Wb1 : Wb0;
        if (kc < 3) issue_tile(kc + 1, (kc & 1) ? Ab0 : Ab1, (kc & 1) ? Wb0 : Wb1);
        if (kc < 3) cpa_wait<1>(); else cpa_wait<0>();
        __syncthreads();

        // transform landed tile in smem: A gets f() + tf32 round, W gets tf32 round
        #pragma unroll
        for (int t = 0; t < 2; t++) {
            int i = tid + t * 256;
            int r = i >> 3;
            int k4 = (i & 7) * 4;
            float4 v = *(float4*)(Ab + r * LDA + k4);
            if (mode == 1) {
                v.x = (v.x == v.x) ? v.x : 0.f;
                v.y = (v.y == v.y) ? v.y : 0.f;
                v.z = (v.z == v.z) ? v.z : 0.f;
                v.w = (v.w == v.w) ? v.w : 0.f;
            } else if (mode == 2) {
                int c = kc * 32 + k4;
                v.x = fmaxf(v.x * scsh[c + 0] + scsh[128 + c + 0], 0.f);
                v.y = fmaxf(v.y * scsh[c + 1] + scsh[128 + c + 1], 0.f);
                v.z = fmaxf(v.z * scsh[c + 2] + scsh[128 + c + 2], 0.f);
                v.w = fmaxf(v.w * scsh[c + 3] + scsh[128 + c + 3], 0.f);
            }
            v.x = wmma::__float_to_tf32(v.x);
            v.y = wmma::__float_to_tf32(v.y);
            v.z = wmma::__float_to_tf32(v.z);
            v.w = wmma::__float_to_tf32(v.w);
            *(float4*)(Ab + r * LDA + k4) = v;
        }
        #pragma unroll
        for (int t = 0; t < 4; t++) {
            int i = tid + t * 256;
            int k = i >> 5, c4 = (i & 31) * 4;
            float4 w = *(float4*)(Wb + k * LDW + c4);
            w.x = wmma::__float_to_tf32(w.x);
            w.y = wmma::__float_to_tf32(w.y);
            w.z = wmma::__float_to_tf32(w.z);
            w.w = wmma::__float_to_tf32(w.w);
            *(float4*)(Wb + k * LDW + c4) = w;
        }
        __syncthreads();

        #pragma unroll
        for (int kk = 0; kk < 4; kk++) {
            wmma::fragment<wmma::matrix_a, 16, 16, 8, wmma::precision::tf32, wmma::row_major> af;
            wmma::load_matrix_sync(af, Ab + (row_blk * 16) * LDA + kk * 8, LDA);
            #pragma unroll
            for (int c = 0; c < 4; c++) {
                wmma::fragment<wmma::matrix_b, 16, 16, 8, wmma::precision::tf32, wmma::row_major> bf;
                wmma::load_matrix_sync(bf, Wb + (kk * 8) * LDW + col_blk * 64 + c * 16, LDW);
                wmma::mma_sync(acc[c], af, bf, acc[c]);
            }
        }
        __syncthreads();   // buffer being overwritten next iter must be fully consumed
    }

    #pragma unroll
    for (int c = 0; c < 4; c++)
        wmma::store_matrix_sync(Cst + (row_blk * 16) * LDW + col_blk * 64 + c * 16,
                                acc[c], LDW, wmma::mem_row_major);
    __syncthreads();

    int cg = tid & 31;
    int rg = tid >> 5;
    #pragma unroll
    for (int r = 0; r < 8; r++) {
        int row = r0 + rg * 8 + r;
        if (row < n) {
            float di = rsqrtf((float)indeg[row] + 1.0f);
            float4 v = *(float4*)(Cst + (rg * 8 + r) * LDW + cg * 4);
            v.x *= di; v.y *= di; v.z *= di; v.w *= di;
            __nv_bfloat162 h0 = __floats2bfloat162_rn(v.x, v.y);
            __nv_bfloat162 h1 = __floats2bfloat162_rn(v.z, v.w);
            uint2 u;
            u.x = *(unsigned int*)&h0;
            u.y = *(unsigned int*)&h1;
            ybf[(size_t)row * 32 + cg] = u;
            float4 s = make_float4(v.x * di, v.y * di, v.z * di, v.w * di);
            *(float4*)(agg + (size_t)row * 128 + cg * 4) = s;
        }
    }
}

// ---------------- sorted edge scatter (bf16 reads, fp32 accumulate) ------------
__device__ __forceinline__ void red_flush(float* agg, const int* indeg,
                                          int node, int lane, float4 a)
{
    float c = rsqrtf((float)__ldg(indeg + node) + 1.0f);
    float* p = agg + (size_t)node * 128 + lane * 4;
    asm volatile("red.global.add.v4.f32 [%0], {%1, %2, %3, %4};"
                 :: "l"(p), "f"(a.x * c), "f"(a.y * c), "f"(a.z * c), "f"(a.w * c)
                 : "memory");
}

__device__ __forceinline__ float4 unpack_bf16x4(uint2 u) {
    __nv_bfloat162 h0 = *(__nv_bfloat162*)&u.x;
    __nv_bfloat162 h1 = *(__nv_bfloat162*)&u.y;
    float2 a = __bfloat1622float2(h0);
    float2 b = __bfloat1622float2(h1);
    return make_float4(a.x, a.y, b.x, b.y);
}

__global__ __launch_bounds__(256) void edge_scatter_sorted(
    const uint2* __restrict__ ybf, const int2* __restrict__ edges,
    const int* __restrict__ indeg, float* __restrict__ agg, int E)
{
    int lane = threadIdx.x & 31;
    int warp = blockIdx.x * 8 + (threadIdx.x >> 5);
    int e0 = warp * EPW;
    if (e0 >= E) return;

    if (e0 + EPW <= E) {
        float4 acc = make_float4(0.f, 0.f, 0.f, 0.f);
        int cur = -1;
        #pragma unroll
        for (int b = 0; b < EPW / 8; b++) {
            int2 ed[8];
            #pragma unroll
            for (int j = 0; j < 8; j++)
                ed[j] = __ldg(edges + e0 + b * 8 + j);
            uint2 raw[8];
            #pragma unroll
            for (int j = 0; j < 8; j++)
                raw[j] = __ldg(ybf + (size_t)ed[j].x * 32 + lane);
            #pragma unroll
            for (int j = 0; j < 8; j++) {
                float4 v = unpack_bf16x4(raw[j]);
                if (ed[j].y == cur) {              // warp-uniform branch
                    acc.x += v.x; acc.y += v.y;
                    acc.z += v.z; acc.w += v.w;
                } else {
                    if (cur >= 0) red_flush(agg, indeg, cur, lane, acc);
                    cur = ed[j].y;
                    acc = v;
                }
            }
        }
        red_flush(agg, indeg, cur, lane, acc);
    } else {
        for (int e = e0; e < E; e++) {
            int2 ed = __ldg(edges + e);
            float4 v = unpack_bf16x4(__ldg(ybf + (size_t)ed.x * 32 + lane));
            red_flush(agg, indeg, ed.y, lane, v);
        }
    }
}

// ---------------- batchnorm stats ------------------------------------------------
__global__ __launch_bounds__(128) void bn_stats(
    const float* __restrict__ src, float* __restrict__ stats, int n)
{
    int col = threadIdx.x;
    float s = 0.f, s2 = 0.f;
    for (int r = blockIdx.x; r < n; r += gridDim.x) {
        float v = src[(size_t)r * 128 + col];
        s += v; s2 += v * v;
    }
    atomicAdd(&stats[col], s);
    atomicAdd(&stats[128 + col], s2);
}

// ---------------- pooling (BN finalize + ReLU fused; batch sorted) -----------------
__global__ __launch_bounds__(256) void counts_kernel(
    const int* __restrict__ batch, float* __restrict__ counts, int n)
{
    __shared__ float sc[NGRAPH];
    if (threadIdx.x < NGRAPH) sc[threadIdx.x] = 0.f;
    __syncthreads();
    for (int i = blockIdx.x * blockDim.x + threadIdx.x; i < n; i += gridDim.x * blockDim.x)
        atomicAdd(&sc[batch[i]], 1.0f);
    __syncthreads();
    if (threadIdx.x < NGRAPH) atomicAdd(&counts[threadIdx.x], sc[threadIdx.x]);
}

__global__ __launch_bounds__(128) void pool_kernel(
    const float* __restrict__ agg, const float* __restrict__ stats,
    const float* __restrict__ gamma, const float* __restrict__ beta,
    const int* __restrict__ batch, float* __restrict__ pooled, int n)
{
    int col = threadIdx.x;
    float invn = 1.0f / (float)n;
    float mean = stats[col] * invn;
    float var  = stats[128 + col] * invn - mean * mean;
    float sc = rsqrtf(var + 1e-5f) * gamma[col];
    float sh = beta[col] - mean * sc;

    int r0 = blockIdx.x * 128;
    if (r0 >= n) return;
    int r1 = min(r0 + 128, n);
    int cg = batch[r0];
    float acc = 0.f;
    for (int r = r0; r < r1; r++) {
        int g = batch[r];
        if (g != cg) {
            atomicAdd(&pooled[cg * 128 + col], acc);
            acc = 0.f;
            cg = g;
        }
        acc += fmaxf(agg[(size_t)r * 128 + col] * sc + sh, 0.f);
    }
    atomicAdd(&pooled[cg * 128 + col], acc);
}

// ---------------- classifier (single block) ----------------------------------------
__global__ __launch_bounds__(256) void classifier_kernel(
    const float* __restrict__ pooled, const float* __restrict__ counts,
    const float* __restrict__ Wc1, const float* __restrict__ bc1,
    const float* __restrict__ Wc2, const float* __restrict__ bc2,
    float* __restrict__ out)
{
    __shared__ float Z[64 * 64];
    __shared__ float inv[NGRAPH];
    int tid = threadIdx.x;
    if (tid < NGRAPH) inv[tid] = 1.0f / fmaxf(counts[tid], 1.0f);
    __syncthreads();

    for (int idx = tid; idx < 64 * 64; idx += 256) {
        int r = idx >> 6, c = idx & 63;
        float dot = 0.f;
        #pragma unroll 8
        for (int k = 0; k < 128; k++)
            dot += pooled[r * 128 + k] * Wc1[k * 64 + c];
        Z[idx] = fmaxf(dot * inv[r] + bc1[c], 0.f);
    }
    __syncthreads();

    for (int idx = tid; idx < 128; idx += 256) {
        int r = idx >> 1, c = idx & 1;
        float dot = bc2[c];
        #pragma unroll
        for (int k = 0; k < 64; k++)
            dot += Z[r * 64 + k] * Wc2[k * 2 + c];
        out[idx] = (dot == dot) ? dot : 0.f;  // nan_to_num
    }
}

// ---------------- launch -------------------------------------------------------------
extern "C" void kernel_launch(void* const* d_in, const int* in_sizes, int n_in,
                              void* d_out, int out_size)
{
    const float* x     = (const float*)d_in[0];
    const int*   ei    = (const int*)d_in[1];
    const int*   batch = (const int*)d_in[2];
    const float* W1  = (const float*)d_in[3];
    // b1 = d_in[4] — exactly cancelled by BatchNorm
    const float* g1  = (const float*)d_in[5];
    const float* be1 = (const float*)d_in[6];
    const float* W2  = (const float*)d_in[7];
    // b2 = d_in[8] — same
    const float* g2  = (const float*)d_in[9];
    const float* be2 = (const float*)d_in[10];
    const float* Wc1 = (const float*)d_in[11];
    const float* bc1 = (const float*)d_in[12];
    const float* Wc2 = (const float*)d_in[13];
    const float* bc2 = (const float*)d_in[14];
    float* out = (float*)d_out;

    int n = in_sizes[0] / HID;
    int E = in_sizes[1] / 2;
    const int* srcp = ei;
    const int* dstp = ei + E;

    float *bufB, *bufC, *stats, *pooled, *counts;
    int *indeg, *btot, *cursor;
    int2 *edges;
    uint2 *ybf;
    cudaGetSymbolAddress((void**)&ybf,    g_ybf);
    cudaGetSymbolAddress((void**)&bufB,   g_bufB4);
    cudaGetSymbolAddress((void**)&bufC,   g_bufC4);
    cudaGetSymbolAddress((void**)&indeg,  g_indeg);
    cudaGetSymbolAddress((void**)&btot,   g_btot);
    cudaGetSymbolAddress((void**)&cursor, g_cursor);
    cudaGetSymbolAddress((void**)&edges,  g_edges);
    cudaGetSymbolAddress((void**)&stats,  g_stats);
    cudaGetSymbolAddress((void**)&pooled, g_pooled);
    cudaGetSymbolAddress((void**)&counts, g_counts);

    int nb256 = (n + 255) / 256;
    int eb256 = (E + 255) / 256;
    int gemm_blocks = (n + 63) / 64;
    int scan_nb = (n + SCAN_BLK - 1) / SCAN_BLK;
    int scat_blocks = (E + 8 * EPW - 1) / (8 * EPW);

    // one-time setup: side stream, events, gemm smem attribute (host objects only)
    static cudaStream_t s2 = nullptr;
    static cudaEvent_t ev_fork = nullptr, ev_join = nullptr;
    if (!s2) {
        cudaStreamCreateWithFlags(&s2, cudaStreamNonBlocking);
        cudaEventCreateWithFlags(&ev_fork, cudaEventDisableTiming);
        cudaEventCreateWithFlags(&ev_join, cudaEventDisableTiming);
        cudaFuncSetAttribute(gemm128, cudaFuncAttributeMaxDynamicSharedMemorySize,
                             GEMM_SMEM_BYTES);
    }
    cudaStream_t s0 = 0;

    // main stream: init + degree count (gemm1 needs indeg)
    zero_all<<<nb256, 256, 0, s0>>>(indeg, stats, pooled, counts, n);
    indeg_count<<<eb256, 256, 0, s0>>>(dstp, indeg, E);

    // fork: side stream builds sorted edge list + counts, overlapping gemm1
    cudaEventRecord(ev_fork, s0);
    cudaStreamWaitEvent(s2, ev_fork, 0);
    block_totals<<<scan_nb, SCAN_BLK, 0, s2>>>(indeg, btot, n);
    scan_blocks<<<scan_nb, SCAN_BLK, 0, s2>>>(indeg, btot, cursor, n, scan_nb);
    sort_fill<<<eb256, 256, 0, s2>>>(srcp, dstp, cursor, edges, E);
    counts_kernel<<<64, 256, 0, s2>>>(batch, counts, n);
    cudaEventRecord(ev_join, s2);

    // main stream: layer-1 GEMM concurrent with build
    gemm128<<<gemm_blocks, 256, GEMM_SMEM_BYTES, s0>>>(
        x, W1, g1, be1, stats, indeg, ybf, bufB, n, 1);

    cudaStreamWaitEvent(s0, ev_join, 0);

    // ---- layer 1 aggregation + BN stats ----
    edge_scatter_sorted<<<scat_blocks, 256, 0, s0>>>(ybf, edges, indeg, bufB, E);
    bn_stats<<<512, 128, 0, s0>>>(bufB, stats, n);

    // ---- layer 2 (BN1 finalize fused into gemm mode 2) ----
    gemm128<<<gemm_blocks, 256, GEMM_SMEM_BYTES, s0>>>(
        bufB, W2, g1, be1, stats, indeg, ybf, bufC, n, 2);
    edge_scatter_sorted<<<scat_blocks, 256, 0, s0>>>(ybf, edges, indeg, bufC, E);
    bn_stats<<<512, 128, 0, s0>>>(bufC, stats + 256, n);

    // ---- pool (BN2 finalize + ReLU fused) + classifier ----
    pool_kernel<<<(n + 127) / 128, 128, 0, s0>>>(bufC, stats + 256, g2, be2,
                                                 batch, pooled, n);
    classifier_kernel<<<1, 256, 0, s0>>>(pooled, counts, Wc1, bc1, Wc2, bc2, out);
}

// round 16
// speedup vs baseline: 3.1040x; 1.0947x over previous
#include <cuda_runtime.h>
#include <cuda_bf16.h>
#include <mma.h>
#include <cstdint>

using namespace nvcuda;

#define NNODES 100000
#define NEDGES 1600000
#define HID 128
#define NGRAPH 64
#define SCAN_BLK 1024
#define EPW 16           // edges per warp (two batches of 8)

#define LDA 36           // padded A tile stride (floats)
#define LDW 132          // padded W / C tile stride (floats)

// ---------------- scratch (device globals) -----------------------------------
__device__ uint2  g_ybf[NNODES * 32];          // y in bf16: 128 bf16/row = 32 uint2
__device__ float4 g_bufB4[NNODES * HID / 4];   // agg layer 1
__device__ float4 g_bufC4[NNODES * HID / 4];   // agg layer 2
__device__ int    g_indeg[NNODES];
__device__ int    g_btot[128];
__device__ int    g_cursor[NNODES];
__device__ int2   g_edges[NEDGES];             // (src,dst) sorted by dst
__device__ float  g_stats[4 * HID];            // layer1: [0,256), layer2: [256,512)
__device__ float  g_pooled[NGRAPH * HID];
__device__ float  g_counts[NGRAPH];

// ---------------- fused zero init ---------------------------------------------
__global__ void zero_all(int* indeg, float* stats, float* pooled, float* counts, int n) {
    int i = blockIdx.x * blockDim.x + threadIdx.x;
    if (i < n) indeg[i] = 0;
    if (i < 4 * HID) stats[i] = 0.f;
    if (i < NGRAPH * HID) pooled[i] = 0.f;
    if (i < NGRAPH) counts[i] = 0.f;
}

__global__ void indeg_count(const int* __restrict__ dst, int* indeg, int E) {
    int e = blockIdx.x * blockDim.x + threadIdx.x;
    if (e < E) atomicAdd(&indeg[dst[e]], 1);
}

__global__ void block_totals(const int* __restrict__ indeg, int* btot, int n) {
    __shared__ int sh[SCAN_BLK];
    int i = blockIdx.x * SCAN_BLK + threadIdx.x;
    sh[threadIdx.x] = (i < n) ? indeg[i] : 0;
    __syncthreads();
    for (int s = SCAN_BLK / 2; s > 0; s >>= 1) {
        if (threadIdx.x < s) sh[threadIdx.x] += sh[threadIdx.x + s];
        __syncthreads();
    }
    if (threadIdx.x == 0) btot[blockIdx.x] = sh[0];
}

__global__ void scan_blocks(const int* __restrict__ indeg, const int* __restrict__ btot,
                            int* cursor, int n, int nb) {
    __shared__ int sh[SCAN_BLK];
    __shared__ int off_sh[128];
    int tid = threadIdx.x;
    int i = blockIdx.x * SCAN_BLK + tid;
    int v = (i < n) ? indeg[i] : 0;
    sh[tid] = v;
    if (tid < 128) off_sh[tid] = (tid < blockIdx.x && tid < nb) ? btot[tid] : 0;
    __syncthreads();
    for (int off = 1; off < SCAN_BLK; off <<= 1) {
        int t = (tid >= off) ? sh[tid - off] : 0;
        __syncthreads();
        sh[tid] += t;
        __syncthreads();
    }
    for (int s = 64; s > 0; s >>= 1) {
        if (tid < s) off_sh[tid] += off_sh[tid + s];
        __syncthreads();
    }
    if (i < n) cursor[i] = off_sh[0] + sh[tid] - v;  // exclusive prefix
}

__global__ void sort_fill(const int* __restrict__ src, const int* __restrict__ dst,
                          int* cursor, int2* edges, int E) {
    int e = blockIdx.x * blockDim.x + threadIdx.x;
    if (e < E) {
        int d = dst[e];
        int pos = atomicAdd(&cursor[d], 1);
        edges[pos] = make_int2(src[e], d);
    }
}

// ---------------- fused GEMM (tf32 tensor cores, padded smem) -------------------
// ybf[row] = bf16((f(A)[row] @ W) * dinv);  agg[row] = same * dinv  (fp32)
// f = nan_to_num (mode 1) / BN+ReLU from raw stats (mode 2; finalize fused here)
__global__ __launch_bounds__(256) void gemm128(
    const float* __restrict__ A, const float* __restrict__ W,
    const float* __restrict__ gamma, const float* __restrict__ beta,
    const float* __restrict__ stats, const int* __restrict__ indeg,
    uint2* __restrict__ ybf, float* __restrict__ agg, int n, int mode)
{
    __shared__ __align__(16) float smem[64 * LDW];
    __shared__ float scsh[2 * HID];
    float* As = smem;              // 64 x LDA
    float* Ws = smem + 64 * LDA;   // 32 x LDW

    int r0 = blockIdx.x * 64;
    int tid = threadIdx.x;
    int warp = tid >> 5;
    int row_blk = warp & 3;
    int col_blk = warp >> 2;

    // mode 2: BN finalize fused — compute per-column scale/shift once per block
    if (mode == 2 && tid < 128) {
        float invn = 1.0f / (float)n;
        float mean = stats[tid] * invn;
        float var  = stats[128 + tid] * invn - mean * mean;
        float sc = rsqrtf(var + 1e-5f) * gamma[tid];
        scsh[tid] = sc;
        scsh[128 + tid] = beta[tid] - mean * sc;
    }
    if (mode == 2) __syncthreads();

    wmma::fragment<wmma::accumulator, 16, 16, 8, float> acc[4];
    #pragma unroll
    for (int c = 0; c < 4; c++) wmma::fill_fragment(acc[c], 0.f);

    for (int kc = 0; kc < 4; kc++) {
        #pragma unroll
        for (int t = 0; t < 2; t++) {
            int i = tid + t * 256;
            int r = i >> 3;
            int k4 = (i & 7) * 4;
            float4 v = make_float4(0.f, 0.f, 0.f, 0.f);
            if (r0 + r < n)
                v = *(const float4*)(A + (size_t)(r0 + r) * 128 + kc * 32 + k4);
            if (mode == 1) {
                v.x = (v.x == v.x) ? v.x : 0.f;
                v.y = (v.y == v.y) ? v.y : 0.f;
                v.z = (v.z == v.z) ? v.z : 0.f;
                v.w = (v.w == v.w) ? v.w : 0.f;
            } else if (mode == 2) {
                int c = kc * 32 + k4;
                v.x = fmaxf(v.x * scsh[c + 0] + scsh[128 + c + 0], 0.f);
                v.y = fmaxf(v.y * scsh[c + 1] + scsh[128 + c + 1], 0.f);
                v.z = fmaxf(v.z * scsh[c + 2] + scsh[128 + c + 2], 0.f);
                v.w = fmaxf(v.w * scsh[c + 3] + scsh[128 + c + 3], 0.f);
            }
            v.x = wmma::__float_to_tf32(v.x);
            v.y = wmma::__float_to_tf32(v.y);
            v.z = wmma::__float_to_tf32(v.z);
            v.w = wmma::__float_to_tf32(v.w);
            *(float4*)(As + r * LDA + k4) = v;
        }
        #pragma unroll
        for (int t = 0; t < 4; t++) {
            int i = tid + t * 256;
            int k = i >> 5, c4 = (i & 31) * 4;
            float4 w = *(const float4*)(W + (size_t)(kc * 32 + k) * 128 + c4);
            w.x = wmma::__float_to_tf32(w.x);
            w.y = wmma::__float_to_tf32(w.y);
            w.z = wmma::__float_to_tf32(w.z);
            w.w = wmma::__float_to_tf32(w.w);
            *(float4*)(Ws + k * LDW + c4) = w;
        }
        __syncthreads();

        #pragma unroll
        for (int kk = 0; kk < 4; kk++) {
            wmma::fragment<wmma::matrix_a, 16, 16, 8, wmma::precision::tf32, wmma::row_major> af;
            wmma::load_matrix_sync(af, As + (row_blk * 16) * LDA + kk * 8, LDA);
            #pragma unroll
            for (int c = 0; c < 4; c++) {
                wmma::fragment<wmma::matrix_b, 16, 16, 8, wmma::precision::tf32, wmma::row_major> bf;
                wmma::load_matrix_sync(bf, Ws + (kk * 8) * LDW + col_blk * 64 + c * 16, LDW);
                wmma::mma_sync(acc[c], af, bf, acc[c]);
            }
        }
        __syncthreads();
    }

    #pragma unroll
    for (int c = 0; c < 4; c++)
        wmma::store_matrix_sync(smem + (row_blk * 16) * LDW + col_blk * 64 + c * 16,
                                acc[c], LDW, wmma::mem_row_major);
    __syncthreads();

    int cg = tid & 31;
    int rg = tid >> 5;
    #pragma unroll
    for (int r = 0; r < 8; r++) {
        int row = r0 + rg * 8 + r;
        if (row < n) {
            float di = rsqrtf((float)indeg[row] + 1.0f);
            float4 v = *(float4*)(smem + (rg * 8 + r) * LDW + cg * 4);
            v.x *= di; v.y *= di; v.z *= di; v.w *= di;
            __nv_bfloat162 h0 = __floats2bfloat162_rn(v.x, v.y);
            __nv_bfloat162 h1 = __floats2bfloat162_rn(v.z, v.w);
            uint2 u;
            u.x = *(unsigned int*)&h0;
            u.y = *(unsigned int*)&h1;
            ybf[(size_t)row * 32 + cg] = u;
            float4 s = make_float4(v.x * di, v.y * di, v.z * di, v.w * di);
            *(float4*)(agg + (size_t)row * 128 + cg * 4) = s;
        }
    }
}

// ---------------- sorted edge scatter (bf16 reads, fp32 accumulate) ------------
__device__ __forceinline__ void red_flush(float* agg, const int* indeg,
                                          int node, int lane, float4 a)
{
    float c = rsqrtf((float)__ldg(indeg + node) + 1.0f);
    float* p = agg + (size_t)node * 128 + lane * 4;
    asm volatile("red.global.add.v4.f32 [%0], {%1, %2, %3, %4};"
                 :: "l"(p), "f"(a.x * c), "f"(a.y * c), "f"(a.z * c), "f"(a.w * c)
                 : "memory");
}

__device__ __forceinline__ float4 unpack_bf16x4(uint2 u) {
    __nv_bfloat162 h0 = *(__nv_bfloat162*)&u.x;
    __nv_bfloat162 h1 = *(__nv_bfloat162*)&u.y;
    float2 a = __bfloat1622float2(h0);
    float2 b = __bfloat1622float2(h1);
    return make_float4(a.x, a.y, b.x, b.y);
}

__global__ __launch_bounds__(256) void edge_scatter_sorted(
    const uint2* __restrict__ ybf, const int2* __restrict__ edges,
    const int* __restrict__ indeg, float* __restrict__ agg, int E)
{
    int lane = threadIdx.x & 31;
    int warp = blockIdx.x * 8 + (threadIdx.x >> 5);
    int e0 = warp * EPW;
    if (e0 >= E) return;

    if (e0 + EPW <= E) {
        float4 acc = make_float4(0.f, 0.f, 0.f, 0.f);
        int cur = -1;
        #pragma unroll
        for (int b = 0; b < EPW / 8; b++) {
            int2 ed[8];
            #pragma unroll
            for (int j = 0; j < 8; j++)
                ed[j] = __ldg(edges + e0 + b * 8 + j);
            uint2 raw[8];
            #pragma unroll
            for (int j = 0; j < 8; j++)
                raw[j] = __ldg(ybf + (size_t)ed[j].x * 32 + lane);
            #pragma unroll
            for (int j = 0; j < 8; j++) {
                float4 v = unpack_bf16x4(raw[j]);
                if (ed[j].y == cur) {              // warp-uniform branch
                    acc.x += v.x; acc.y += v.y;
                    acc.z += v.z; acc.w += v.w;
                } else {
                    if (cur >= 0) red_flush(agg, indeg, cur, lane, acc);
                    cur = ed[j].y;
                    acc = v;
                }
            }
        }
        red_flush(agg, indeg, cur, lane, acc);
    } else {
        for (int e = e0; e < E; e++) {
            int2 ed = __ldg(edges + e);
            float4 v = unpack_bf16x4(__ldg(ybf + (size_t)ed.x * 32 + lane));
            red_flush(agg, indeg, ed.y, lane, v);
        }
    }
}

// ---------------- batchnorm stats ------------------------------------------------
__global__ __launch_bounds__(128) void bn_stats(
    const float* __restrict__ src, float* __restrict__ stats, int n)
{
    int col = threadIdx.x;
    float s = 0.f, s2 = 0.f;
    for (int r = blockIdx.x; r < n; r += gridDim.x) {
        float v = src[(size_t)r * 128 + col];
        s += v; s2 += v * v;
    }
    atomicAdd(&stats[col], s);
    atomicAdd(&stats[128 + col], s2);
}

// ---------------- pooling (BN finalize + ReLU fused; batch sorted) -----------------
__global__ __launch_bounds__(256) void counts_kernel(
    const int* __restrict__ batch, float* __restrict__ counts, int n)
{
    __shared__ float sc[NGRAPH];
    if (threadIdx.x < NGRAPH) sc[threadIdx.x] = 0.f;
    __syncthreads();
    for (int i = blockIdx.x * blockDim.x + threadIdx.x; i < n; i += gridDim.x * blockDim.x)
        atomicAdd(&sc[batch[i]], 1.0f);
    __syncthreads();
    if (threadIdx.x < NGRAPH) atomicAdd(&counts[threadIdx.x], sc[threadIdx.x]);
}

__global__ __launch_bounds__(128) void pool_kernel(
    const float* __restrict__ agg, const float* __restrict__ stats,
    const float* __restrict__ gamma, const float* __restrict__ beta,
    const int* __restrict__ batch, float* __restrict__ pooled, int n)
{
    int col = threadIdx.x;
    float invn = 1.0f / (float)n;
    float mean = stats[col] * invn;
    float var  = stats[128 + col] * invn - mean * mean;
    float sc = rsqrtf(var + 1e-5f) * gamma[col];
    float sh = beta[col] - mean * sc;

    int r0 = blockIdx.x * 128;
    if (r0 >= n) return;
    int r1 = min(r0 + 128, n);
    int cg = batch[r0];
    float acc = 0.f;
    for (int r = r0; r < r1; r++) {
        int g = batch[r];
        if (g != cg) {
            atomicAdd(&pooled[cg * 128 + col], acc);
            acc = 0.f;
            cg = g;
        }
        acc += fmaxf(agg[(size_t)r * 128 + col] * sc + sh, 0.f);
    }
    atomicAdd(&pooled[cg * 128 + col], acc);
}

// ---------------- classifier (single block) ----------------------------------------
__global__ __launch_bounds__(256) void classifier_kernel(
    const float* __restrict__ pooled, const float* __restrict__ counts,
    const float* __restrict__ Wc1, const float* __restrict__ bc1,
    const float* __restrict__ Wc2, const float* __restrict__ bc2,
    float* __restrict__ out)
{
    __shared__ float Z[64 * 64];
    __shared__ float inv[NGRAPH];
    int tid = threadIdx.x;
    if (tid < NGRAPH) inv[tid] = 1.0f / fmaxf(counts[tid], 1.0f);
    __syncthreads();

    for (int idx = tid; idx < 64 * 64; idx += 256) {
        int r = idx >> 6, c = idx & 63;
        float dot = 0.f;
        #pragma unroll 8
        for (int k = 0; k < 128; k++)
            dot += pooled[r * 128 + k] * Wc1[k * 64 + c];
        Z[idx] = fmaxf(dot * inv[r] + bc1[c], 0.f);
    }
    __syncthreads();

    for (int idx = tid; idx < 128; idx += 256) {
        int r = idx >> 1, c = idx & 1;
        float dot = bc2[c];
        #pragma unroll
        for (int k = 0; k < 64; k++)
            dot += Z[r * 64 + k] * Wc2[k * 2 + c];
        out[idx] = (dot == dot) ? dot : 0.f;  // nan_to_num
    }
}

// ---------------- launch -------------------------------------------------------------
extern "C" void kernel_launch(void* const* d_in, const int* in_sizes, int n_in,
                              void* d_out, int out_size)
{
    const float* x     = (const float*)d_in[0];
    const int*   ei    = (const int*)d_in[1];
    const int*   batch = (const int*)d_in[2];
    const float* W1  = (const float*)d_in[3];
    // b1 = d_in[4] — exactly cancelled by BatchNorm
    const float* g1  = (const float*)d_in[5];
    const float* be1 = (const float*)d_in[6];
    const float* W2  = (const float*)d_in[7];
    // b2 = d_in[8] — same
    const float* g2  = (const float*)d_in[9];
    const float* be2 = (const float*)d_in[10];
    const float* Wc1 = (const float*)d_in[11];
    const float* bc1 = (const float*)d_in[12];
    const float* Wc2 = (const float*)d_in[13];
    const float* bc2 = (const float*)d_in[14];
    float* out = (float*)d_out;

    int n = in_sizes[0] / HID;
    int E = in_sizes[1] / 2;
    const int* srcp = ei;
    const int* dstp = ei + E;

    float *bufB, *bufC, *stats, *pooled, *counts;
    int *indeg, *btot, *cursor;
    int2 *edges;
    uint2 *ybf;
    cudaGetSymbolAddress((void**)&ybf,    g_ybf);
    cudaGetSymbolAddress((void**)&bufB,   g_bufB4);
    cudaGetSymbolAddress((void**)&bufC,   g_bufC4);
    cudaGetSymbolAddress((void**)&indeg,  g_indeg);
    cudaGetSymbolAddress((void**)&btot,   g_btot);
    cudaGetSymbolAddress((void**)&cursor, g_cursor);
    cudaGetSymbolAddress((void**)&edges,  g_edges);
    cudaGetSymbolAddress((void**)&stats,  g_stats);
    cudaGetSymbolAddress((void**)&pooled, g_pooled);
    cudaGetSymbolAddress((void**)&counts, g_counts);

    int nb256 = (n + 255) / 256;
    int eb256 = (E + 255) / 256;
    int gemm_blocks = (n + 63) / 64;
    int scan_nb = (n + SCAN_BLK - 1) / SCAN_BLK;
    int scat_blocks = (E + 8 * EPW - 1) / (8 * EPW);

    // side stream + events (created once; host-side objects only)
    static cudaStream_t s2 = nullptr;
    static cudaEvent_t ev_fork = nullptr, ev_join = nullptr;
    if (!s2) {
        cudaStreamCreateWithFlags(&s2, cudaStreamNonBlocking);
        cudaEventCreateWithFlags(&ev_fork, cudaEventDisableTiming);
        cudaEventCreateWithFlags(&ev_join, cudaEventDisableTiming);
    }
    cudaStream_t s0 = 0;

    // main stream: init + degree count (gemm1 needs indeg)
    zero_all<<<nb256, 256, 0, s0>>>(indeg, stats, pooled, counts, n);
    indeg_count<<<eb256, 256, 0, s0>>>(dstp, indeg, E);

    // fork: side stream builds sorted edge list + counts, overlapping gemm1
    cudaEventRecord(ev_fork, s0);
    cudaStreamWaitEvent(s2, ev_fork, 0);
    block_totals<<<scan_nb, SCAN_BLK, 0, s2>>>(indeg, btot, n);
    scan_blocks<<<scan_nb, SCAN_BLK, 0, s2>>>(indeg, btot, cursor, n, scan_nb);
    sort_fill<<<eb256, 256, 0, s2>>>(srcp, dstp, cursor, edges, E);
    counts_kernel<<<64, 256, 0, s2>>>(batch, counts, n);
    cudaEventRecord(ev_join, s2);

    // main stream: layer-1 GEMM concurrent with build
    gemm128<<<gemm_blocks, 256, 0, s0>>>(x, W1, g1, be1, stats, indeg, ybf, bufB, n, 1);

    cudaStreamWaitEvent(s0, ev_join, 0);

    // ---- layer 1 aggregation + BN stats ----
    edge_scatter_sorted<<<scat_blocks, 256, 0, s0>>>(ybf, edges, indeg, bufB, E);
    bn_stats<<<512, 128, 0, s0>>>(bufB, stats, n);

    // ---- layer 2 (BN1 finalize fused into gemm mode 2) ----
    gemm128<<<gemm_blocks, 256, 0, s0>>>(bufB, W2, g1, be1, stats, indeg, ybf, bufC, n, 2);
    edge_scatter_sorted<<<scat_blocks, 256, 0, s0>>>(ybf, edges, indeg, bufC, E);
    bn_stats<<<512, 128, 0, s0>>>(bufC, stats + 256, n);

    // ---- pool (BN2 finalize + ReLU fused) + classifier ----
    pool_kernel<<<(n + 127) / 128, 128, 0, s0>>>(bufC, stats + 256, g2, be2,
                                                 batch, pooled, n);
    classifier_kernel<<<1, 256, 0, s0>>>(pooled, counts, Wc1, bc1, Wc2, bc2, out);
}